// round 9
// baseline (speedup 1.0000x reference)
#include <cuda_runtime.h>
#include <cuda_fp16.h>
#include <cstdint>

// ============================================================
// Linear2Bit: y[8192,4096] = x[8192,4096] @ Wq[4096,4096]^T * scale + bias
// fp16 mma.sync.m16n8k16 path + device-side dtype probe for weights.
// R8 = R7 resubmit (infra failure last round; kernel unchanged):
// warp tile 64x64, 8 warps, single sync/iter, wide prep stores.
// ============================================================

#define TOKENS 8192
#define INFEAT 4096
#define OUTFEAT 4096

#define BM 128
#define BN 256
#define BK 64
#define NSTAGE 4
#define KITERS (INFEAT / BK)   // 64
#define NTHREADS 256

#define ASZ (BM * BK * 2)      // 16 KB / stage
#define BSZ (BN * BK * 2)      // 32 KB / stage
#define OFF_A 0
#define OFF_B (NSTAGE * ASZ)   // 65536
#define SMEM_TOTAL (OFF_B + NSTAGE * BSZ)   // 196608 B

// scratch (allocation-free rule: __device__ globals)
__device__ __align__(256) __half g_xh[TOKENS * INFEAT];   // 64 MB
__device__ __align__(256) __half g_wh[OUTFEAT * INFEAT];  // 32 MB
__device__ int g_wflags[3] = {1, 1, 1};   // [0]=f32, [1]=bf16, [2]=i32; cleared by probe

// ---------------- PTX helpers (compute_100-safe) ----------------
__device__ __forceinline__ uint32_t smem_u32(const void* p) {
    uint32_t a;
    asm("{ .reg .u64 t; cvta.to.shared.u64 t, %1; cvt.u32.u64 %0, t; }"
        : "=r"(a) : "l"(p));
    return a;
}

#define CP_ASYNC16(dst, src) \
    asm volatile("cp.async.cg.shared.global [%0], [%1], 16;" :: "r"(dst), "l"(src))
#define CP_COMMIT() asm volatile("cp.async.commit_group;")
#define CP_WAIT(n)  asm volatile("cp.async.wait_group %0;" :: "n"(n))

__device__ __forceinline__ void ldsm4(uint32_t* r, uint32_t addr) {
    asm volatile("ldmatrix.sync.aligned.m8n8.x4.shared.b16 {%0,%1,%2,%3}, [%4];"
                 : "=r"(r[0]), "=r"(r[1]), "=r"(r[2]), "=r"(r[3]) : "r"(addr));
}

__device__ __forceinline__ void mma16816(float* d, const uint32_t* a,
                                         uint32_t b0, uint32_t b1) {
    asm volatile(
        "mma.sync.aligned.m16n8k16.row.col.f32.f16.f16.f32 "
        "{%0,%1,%2,%3}, {%4,%5,%6,%7}, {%8,%9}, {%0,%1,%2,%3};"
        : "+f"(d[0]), "+f"(d[1]), "+f"(d[2]), "+f"(d[3])
        : "r"(a[0]), "r"(a[1]), "r"(a[2]), "r"(a[3]), "r"(b0), "r"(b1));
}

// ---------------- dtype probe ----------------
// Weight values {-2,-1,0,1}; disjoint 32-bit signatures per dtype.
#define PROBE_WORDS 65536

__device__ __forceinline__ bool bf16_ok(uint32_t h) {
    return h == 0x0000u || h == 0x3F80u || h == 0xBF80u || h == 0xC000u;
}

__global__ void __launch_bounds__(256) probe_w_kernel(const uint32_t* __restrict__ w) {
    bool f32 = true, bf16 = true, i32 = true;
    for (int i = blockIdx.x * 256 + threadIdx.x; i < PROBE_WORDS; i += gridDim.x * 256) {
        uint32_t v = w[i];
        f32 &= (v == 0u || v == 0x3F800000u || v == 0xBF800000u || v == 0xC0000000u);
        bf16 &= bf16_ok(v & 0xFFFFu) && bf16_ok(v >> 16);
        i32 &= (v == 0u || v == 1u || v == 0xFFFFFFFFu || v == 0xFFFFFFFEu);
    }
    if (!f32)  g_wflags[0] = 0;   // clears only; idempotent across graph replays
    if (!bf16) g_wflags[1] = 0;
    if (!i32)  g_wflags[2] = 0;
}

__global__ void noop_kernel() {}

// ---------------- prep kernels (8 elems / thread, 16B stores) ----------------
union HalfPack {
    uint4 u;
    __half2 h[4];
};

__global__ void __launch_bounds__(256) prep_x_kernel(const float* __restrict__ x,
                                                     __half* __restrict__ xh) {
    int i = blockIdx.x * 256 + threadIdx.x;      // 8 floats per thread
    float4 v0 = reinterpret_cast<const float4*>(x)[2 * i + 0];
    float4 v1 = reinterpret_cast<const float4*>(x)[2 * i + 1];
    HalfPack o;
    o.h[0] = __floats2half2_rn(v0.x, v0.y);
    o.h[1] = __floats2half2_rn(v0.z, v0.w);
    o.h[2] = __floats2half2_rn(v1.x, v1.y);
    o.h[3] = __floats2half2_rn(v1.z, v1.w);
    reinterpret_cast<uint4*>(xh)[i] = o.u;
}

__device__ __forceinline__ float bf16_to_f(uint32_t h) {
    return __uint_as_float(h << 16);
}

__global__ void __launch_bounds__(256) prep_w_kernel(const void* __restrict__ w,
                                                     __half* __restrict__ wh) {
    int i = blockIdx.x * 256 + threadIdx.x;      // 8 weight elements per thread
    float f[8];
    if (g_wflags[0]) {               // float32
        float4 a = reinterpret_cast<const float4*>(w)[2 * i + 0];
        float4 b = reinterpret_cast<const float4*>(w)[2 * i + 1];
        f[0] = a.x; f[1] = a.y; f[2] = a.z; f[3] = a.w;
        f[4] = b.x; f[5] = b.y; f[6] = b.z; f[7] = b.w;
    } else if (g_wflags[1]) {        // bfloat16
        uint4 v = reinterpret_cast<const uint4*>(w)[i];
        f[0] = bf16_to_f(v.x & 0xFFFFu); f[1] = bf16_to_f(v.x >> 16);
        f[2] = bf16_to_f(v.y & 0xFFFFu); f[3] = bf16_to_f(v.y >> 16);
        f[4] = bf16_to_f(v.z & 0xFFFFu); f[5] = bf16_to_f(v.z >> 16);
        f[6] = bf16_to_f(v.w & 0xFFFFu); f[7] = bf16_to_f(v.w >> 16);
    } else if (g_wflags[2]) {        // int32
        int4 a = reinterpret_cast<const int4*>(w)[2 * i + 0];
        int4 b = reinterpret_cast<const int4*>(w)[2 * i + 1];
        f[0] = (float)a.x; f[1] = (float)a.y; f[2] = (float)a.z; f[3] = (float)a.w;
        f[4] = (float)b.x; f[5] = (float)b.y; f[6] = (float)b.z; f[7] = (float)b.w;
    } else {                         // int8
        uint2 v = reinterpret_cast<const uint2*>(w)[i];
        #pragma unroll
        for (int q = 0; q < 4; q++) f[q]     = (float)(int8_t)((v.x >> (8 * q)) & 0xFF);
        #pragma unroll
        for (int q = 0; q < 4; q++) f[4 + q] = (float)(int8_t)((v.y >> (8 * q)) & 0xFF);
    }
    HalfPack o;
    o.h[0] = __floats2half2_rn(f[0], f[1]);
    o.h[1] = __floats2half2_rn(f[2], f[3]);
    o.h[2] = __floats2half2_rn(f[4], f[5]);
    o.h[3] = __floats2half2_rn(f[6], f[7]);
    reinterpret_cast<uint4*>(wh)[i] = o.u;
}

// ---------------- main GEMM ----------------
// 256 threads = 8 warps as 2(M) x 4(N); warp tile 64 x 64.
// smem per stage: rows of 64 halves (128 B), 16B-chunk swizzle:
//   addr(r, c16) = r*128 + ((c16 ^ (r & 7)) << 4)
__global__ void __launch_bounds__(NTHREADS, 1) gemm_kernel(
    const __half* __restrict__ A,   // [TOKENS, INFEAT]  K-major
    const __half* __restrict__ B,   // [OUTFEAT, INFEAT] K-major
    const float* __restrict__ scale,
    const float* __restrict__ bias,
    float* __restrict__ out)
{
    extern __shared__ char smem[];
    const uint32_t sb = smem_u32(smem);
    const int tid = threadIdx.x;
    const int m0 = blockIdx.y * BM;
    const int n0 = blockIdx.x * BN;

    const int wid = tid >> 5, lid = tid & 31;
    const int mw = wid & 1;        // warp M index (0-1)
    const int nw = wid >> 1;       // warp N index (0-3)

    const char* gAb = (const char*)__cvta_generic_to_global(A + (size_t)m0 * INFEAT);
    const char* gBb = (const char*)__cvta_generic_to_global(B + (size_t)n0 * INFEAT);

    // canonical ldmatrix.x4 lane map: local row = lid&15, k-chunk = lid>>4
    const int rloc = lid & 15;
    const uint32_t chSel = (uint32_t)(lid >> 4);

    uint32_t aBase[4], aXor[4];
    #pragma unroll
    for (int tm = 0; tm < 4; tm++) {
        int r = mw * 64 + tm * 16 + rloc;
        aBase[tm] = (uint32_t)(r * 128);
        aXor[tm] = (uint32_t)(r & 7);
    }
    uint32_t bBase[4], bXor[4];
    #pragma unroll
    for (int tp = 0; tp < 4; tp++) {
        int r = nw * 64 + tp * 16 + rloc;
        bBase[tp] = (uint32_t)(r * 128);
        bXor[tp] = (uint32_t)(r & 7);
    }

    float acc[4][8][4];
    #pragma unroll
    for (int i = 0; i < 4; i++)
        #pragma unroll
        for (int j = 0; j < 8; j++)
            #pragma unroll
            for (int q = 0; q < 4; q++) acc[i][j][q] = 0.f;

    auto load_stage = [&](int it) {
        const int s = it & (NSTAGE - 1);
        const int k0 = it * BK;
        const uint32_t sa = sb + OFF_A + s * ASZ;
        const uint32_t sbu = sb + OFF_B + s * BSZ;
        #pragma unroll
        for (int j = 0; j < 4; j++) {                 // A: 1024 chunks / 256 thr
            int c = tid + j * NTHREADS;
            int r = c >> 3, c16 = c & 7;
            uint32_t dst = sa + (uint32_t)(r * 128 + ((c16 ^ (r & 7)) << 4));
            CP_ASYNC16(dst, gAb + ((size_t)r * INFEAT + k0 + c16 * 8) * 2);
        }
        #pragma unroll
        for (int j = 0; j < 8; j++) {                 // B: 2048 chunks / 256 thr
            int c = tid + j * NTHREADS;
            int r = c >> 3, c16 = c & 7;
            uint32_t dst = sbu + (uint32_t)(r * 128 + ((c16 ^ (r & 7)) << 4));
            CP_ASYNC16(dst, gBb + ((size_t)r * INFEAT + k0 + c16 * 8) * 2);
        }
    };

    #pragma unroll
    for (int p = 0; p < NSTAGE - 1; p++) { load_stage(p); CP_COMMIT(); }

    for (int it = 0; it < KITERS; ++it) {
        CP_WAIT(NSTAGE - 2);          // stage `it` resident
        __syncthreads();              // also proves iter it-1 reads complete

        if (it + NSTAGE - 1 < KITERS) load_stage(it + NSTAGE - 1);
        CP_COMMIT();                  // commit every iter (group accounting)

        const int s = it & (NSTAGE - 1);
        const uint32_t sa = sb + OFF_A + s * ASZ;
        const uint32_t sbu = sb + OFF_B + s * BSZ;

        #pragma unroll
        for (int ks = 0; ks < 4; ks++) {
            const uint32_t c16 = (uint32_t)(ks * 2) + chSel;
            uint32_t afr[4][4], bfr[4][4];
            #pragma unroll
            for (int tm = 0; tm < 4; tm++)
                ldsm4(afr[tm], sa + aBase[tm] + ((c16 ^ aXor[tm]) << 4));
            #pragma unroll
            for (int tp = 0; tp < 4; tp++)
                ldsm4(bfr[tp], sbu + bBase[tp] + ((c16 ^ bXor[tp]) << 4));
            #pragma unroll
            for (int tm = 0; tm < 4; tm++)
                #pragma unroll
                for (int tn = 0; tn < 8; tn++) {
                    const int tp = tn >> 1, h = tn & 1;
                    mma16816(acc[tm][tn], afr[tm], bfr[tp][h], bfr[tp][h + 2]);
                }
        }
    }

    // ---- epilogue ----
    const float scl = *scale;
    const int rr = lid >> 2;
    const int cc = (lid & 3) * 2;
    #pragma unroll
    for (int tm = 0; tm < 4; tm++) {
        const int row = m0 + mw * 64 + tm * 16 + rr;
        #pragma unroll
        for (int tn = 0; tn < 8; tn++) {
            const int col = n0 + nw * 64 + tn * 8 + cc;
            const float2 bi = *reinterpret_cast<const float2*>(bias + col);
            float2 v0, v1;
            v0.x = fmaf(acc[tm][tn][0], scl, bi.x);
            v0.y = fmaf(acc[tm][tn][1], scl, bi.y);
            v1.x = fmaf(acc[tm][tn][2], scl, bi.x);
            v1.y = fmaf(acc[tm][tn][3], scl, bi.y);
            *reinterpret_cast<float2*>(out + (size_t)row * OUTFEAT + col) = v0;
            *reinterpret_cast<float2*>(out + (size_t)(row + 8) * OUTFEAT + col) = v1;
        }
    }
}

// ---------------- launch ----------------
extern "C" void kernel_launch(void* const* d_in, const int* in_sizes, int n_in,
                              void* d_out, int out_size) {
    // Identify inputs by element count (dtype-invariant):
    const float* x = nullptr;
    const void*  wq = nullptr;
    const float* scale = nullptr;
    const float* bias = nullptr;
    for (int i = 0; i < n_in; i++) {
        const int sz = in_sizes[i];
        if (sz == TOKENS * INFEAT)       x     = (const float*)d_in[i];
        else if (sz == OUTFEAT * INFEAT) wq    = d_in[i];
        else if (sz == 1)                scale = (const float*)d_in[i];
        else if (sz == OUTFEAT)          bias  = (const float*)d_in[i];
    }
    float* out = (float*)d_out;

    __half* xh = nullptr;
    __half* wh = nullptr;
    cudaGetSymbolAddress((void**)&xh, g_xh);
    cudaGetSymbolAddress((void**)&wh, g_wh);

    // Launch order (6 per call) aligns the GEMM at global launch index 5
    // so ncu (-s 5 -c 1) captures it.
    probe_w_kernel<<<64, 256>>>((const uint32_t*)wq);                 // 0
    prep_x_kernel<<<(TOKENS * INFEAT) / 8 / 256, 256>>>(x, xh);       // 1
    prep_w_kernel<<<(OUTFEAT * INFEAT) / 8 / 256, 256>>>(wq, wh);     // 2
    noop_kernel<<<1, 1>>>();                                          // 3
    noop_kernel<<<1, 1>>>();                                          // 4

    cudaFuncSetAttribute(gemm_kernel, cudaFuncAttributeMaxDynamicSharedMemorySize,
                         SMEM_TOTAL);
    dim3 grid(OUTFEAT / BN, TOKENS / BM);   // (16, 64): N fastest -> A-panel L2 reuse
    gemm_kernel<<<grid, NTHREADS, SMEM_TOTAL>>>(xh, wh, scale, bias, out);  // 5
}

// round 13
// speedup vs baseline: 1.0517x; 1.0517x over previous
#include <cuda_runtime.h>
#include <cuda_fp16.h>
#include <cstdint>

// ============================================================
// Linear2Bit: y[8192,4096] = x[8192,4096] @ Wq[4096,4096]^T * scale + bias
// fp16 mma.sync.m16n8k16 path + device-side dtype probe for weights.
// R13 = R10/R12 resubmit (infra failure; kernel unchanged):
// 2 CTAs/SM (CTA 128x128, 128 thr, 4 warps 64x64, NSTAGE=3) for
// cross-CTA latency hiding; gemm at local launch index 3 for ncu capture.
// ============================================================

#define TOKENS 8192
#define INFEAT 4096
#define OUTFEAT 4096

#define BM 128
#define BN 128
#define BK 64
#define NSTAGE 3
#define KITERS (INFEAT / BK)   // 64
#define NTHREADS 128

#define ASZ (BM * BK * 2)      // 16 KB / stage
#define BSZ (BN * BK * 2)      // 16 KB / stage
#define OFF_A 0
#define OFF_B (NSTAGE * ASZ)   // 49152
#define SMEM_TOTAL (OFF_B + NSTAGE * BSZ)   // 98304 B -> 2 CTAs/SM

// scratch (allocation-free rule: __device__ globals)
__device__ __align__(256) __half g_xh[TOKENS * INFEAT];   // 64 MB
__device__ __align__(256) __half g_wh[OUTFEAT * INFEAT];  // 32 MB
__device__ int g_wflags[3] = {1, 1, 1};   // [0]=f32, [1]=bf16, [2]=i32; cleared by probe

// ---------------- PTX helpers (compute_100-safe) ----------------
__device__ __forceinline__ uint32_t smem_u32(const void* p) {
    uint32_t a;
    asm("{ .reg .u64 t; cvta.to.shared.u64 t, %1; cvt.u32.u64 %0, t; }"
        : "=r"(a) : "l"(p));
    return a;
}

#define CP_ASYNC16(dst, src) \
    asm volatile("cp.async.cg.shared.global [%0], [%1], 16;" :: "r"(dst), "l"(src))
#define CP_COMMIT() asm volatile("cp.async.commit_group;")
#define CP_WAIT(n)  asm volatile("cp.async.wait_group %0;" :: "n"(n))

__device__ __forceinline__ void ldsm4(uint32_t* r, uint32_t addr) {
    asm volatile("ldmatrix.sync.aligned.m8n8.x4.shared.b16 {%0,%1,%2,%3}, [%4];"
                 : "=r"(r[0]), "=r"(r[1]), "=r"(r[2]), "=r"(r[3]) : "r"(addr));
}

__device__ __forceinline__ void mma16816(float* d, const uint32_t* a,
                                         uint32_t b0, uint32_t b1) {
    asm volatile(
        "mma.sync.aligned.m16n8k16.row.col.f32.f16.f16.f32 "
        "{%0,%1,%2,%3}, {%4,%5,%6,%7}, {%8,%9}, {%0,%1,%2,%3};"
        : "+f"(d[0]), "+f"(d[1]), "+f"(d[2]), "+f"(d[3])
        : "r"(a[0]), "r"(a[1]), "r"(a[2]), "r"(a[3]), "r"(b0), "r"(b1));
}

// ---------------- dtype probe ----------------
// Weight values {-2,-1,0,1}; disjoint 32-bit signatures per dtype.
#define PROBE_WORDS 65536

__device__ __forceinline__ bool bf16_ok(uint32_t h) {
    return h == 0x0000u || h == 0x3F80u || h == 0xBF80u || h == 0xC000u;
}

__global__ void __launch_bounds__(256) probe_w_kernel(const uint32_t* __restrict__ w) {
    bool f32 = true, bf16 = true, i32 = true;
    for (int i = blockIdx.x * 256 + threadIdx.x; i < PROBE_WORDS; i += gridDim.x * 256) {
        uint32_t v = w[i];
        f32 &= (v == 0u || v == 0x3F800000u || v == 0xBF800000u || v == 0xC0000000u);
        bf16 &= bf16_ok(v & 0xFFFFu) && bf16_ok(v >> 16);
        i32 &= (v == 0u || v == 1u || v == 0xFFFFFFFFu || v == 0xFFFFFFFEu);
    }
    if (!f32)  g_wflags[0] = 0;   // clears only; idempotent across graph replays
    if (!bf16) g_wflags[1] = 0;
    if (!i32)  g_wflags[2] = 0;
}

// ---------------- prep kernels (8 elems / thread, 16B stores) ----------------
union HalfPack {
    uint4 u;
    __half2 h[4];
};

__global__ void __launch_bounds__(256) prep_x_kernel(const float* __restrict__ x,
                                                     __half* __restrict__ xh) {
    int i = blockIdx.x * 256 + threadIdx.x;      // 8 floats per thread
    float4 v0 = reinterpret_cast<const float4*>(x)[2 * i + 0];
    float4 v1 = reinterpret_cast<const float4*>(x)[2 * i + 1];
    HalfPack o;
    o.h[0] = __floats2half2_rn(v0.x, v0.y);
    o.h[1] = __floats2half2_rn(v0.z, v0.w);
    o.h[2] = __floats2half2_rn(v1.x, v1.y);
    o.h[3] = __floats2half2_rn(v1.z, v1.w);
    reinterpret_cast<uint4*>(xh)[i] = o.u;
}

__device__ __forceinline__ float bf16_to_f(uint32_t h) {
    return __uint_as_float(h << 16);
}

__global__ void __launch_bounds__(256) prep_w_kernel(const void* __restrict__ w,
                                                     __half* __restrict__ wh) {
    int i = blockIdx.x * 256 + threadIdx.x;      // 8 weight elements per thread
    float f[8];
    if (g_wflags[0]) {               // float32
        float4 a = reinterpret_cast<const float4*>(w)[2 * i + 0];
        float4 b = reinterpret_cast<const float4*>(w)[2 * i + 1];
        f[0] = a.x; f[1] = a.y; f[2] = a.z; f[3] = a.w;
        f[4] = b.x; f[5] = b.y; f[6] = b.z; f[7] = b.w;
    } else if (g_wflags[1]) {        // bfloat16
        uint4 v = reinterpret_cast<const uint4*>(w)[i];
        f[0] = bf16_to_f(v.x & 0xFFFFu); f[1] = bf16_to_f(v.x >> 16);
        f[2] = bf16_to_f(v.y & 0xFFFFu); f[3] = bf16_to_f(v.y >> 16);
        f[4] = bf16_to_f(v.z & 0xFFFFu); f[5] = bf16_to_f(v.z >> 16);
        f[6] = bf16_to_f(v.w & 0xFFFFu); f[7] = bf16_to_f(v.w >> 16);
    } else if (g_wflags[2]) {        // int32
        int4 a = reinterpret_cast<const int4*>(w)[2 * i + 0];
        int4 b = reinterpret_cast<const int4*>(w)[2 * i + 1];
        f[0] = (float)a.x; f[1] = (float)a.y; f[2] = (float)a.z; f[3] = (float)a.w;
        f[4] = (float)b.x; f[5] = (float)b.y; f[6] = (float)b.z; f[7] = (float)b.w;
    } else {                         // int8
        uint2 v = reinterpret_cast<const uint2*>(w)[i];
        #pragma unroll
        for (int q = 0; q < 4; q++) f[q]     = (float)(int8_t)((v.x >> (8 * q)) & 0xFF);
        #pragma unroll
        for (int q = 0; q < 4; q++) f[4 + q] = (float)(int8_t)((v.y >> (8 * q)) & 0xFF);
    }
    HalfPack o;
    o.h[0] = __floats2half2_rn(f[0], f[1]);
    o.h[1] = __floats2half2_rn(f[2], f[3]);
    o.h[2] = __floats2half2_rn(f[4], f[5]);
    o.h[3] = __floats2half2_rn(f[6], f[7]);
    reinterpret_cast<uint4*>(wh)[i] = o.u;
}

// ---------------- main GEMM ----------------
// 128 threads = 4 warps as 2(M) x 2(N); warp tile 64 x 64; 2 CTAs/SM.
// smem per stage: rows of 64 halves (128 B), 16B-chunk swizzle:
//   addr(r, c16) = r*128 + ((c16 ^ (r & 7)) << 4)
__global__ void __launch_bounds__(NTHREADS, 2) gemm_kernel(
    const __half* __restrict__ A,   // [TOKENS, INFEAT]  K-major
    const __half* __restrict__ B,   // [OUTFEAT, INFEAT] K-major
    const float* __restrict__ scale,
    const float* __restrict__ bias,
    float* __restrict__ out)
{
    extern __shared__ char smem[];
    const uint32_t sb = smem_u32(smem);
    const int tid = threadIdx.x;
    const int m0 = blockIdx.y * BM;
    const int n0 = blockIdx.x * BN;

    const int wid = tid >> 5, lid = tid & 31;
    const int mw = wid & 1;        // warp M index (0-1)
    const int nw = wid >> 1;       // warp N index (0-1)

    const char* gAb = (const char*)__cvta_generic_to_global(A + (size_t)m0 * INFEAT);
    const char* gBb = (const char*)__cvta_generic_to_global(B + (size_t)n0 * INFEAT);

    // canonical ldmatrix.x4 lane map: local row = lid&15, k-chunk = lid>>4
    const int rloc = lid & 15;
    const uint32_t chSel = (uint32_t)(lid >> 4);

    uint32_t aBase[4], aXor[4];
    #pragma unroll
    for (int tm = 0; tm < 4; tm++) {
        int r = mw * 64 + tm * 16 + rloc;
        aBase[tm] = (uint32_t)(r * 128);
        aXor[tm] = (uint32_t)(r & 7);
    }
    uint32_t bBase[4], bXor[4];
    #pragma unroll
    for (int tp = 0; tp < 4; tp++) {
        int r = nw * 64 + tp * 16 + rloc;
        bBase[tp] = (uint32_t)(r * 128);
        bXor[tp] = (uint32_t)(r & 7);
    }

    float acc[4][8][4];
    #pragma unroll
    for (int i = 0; i < 4; i++)
        #pragma unroll
        for (int j = 0; j < 8; j++)
            #pragma unroll
            for (int q = 0; q < 4; q++) acc[i][j][q] = 0.f;

    auto load_stage = [&](int it, int s) {
        const int k0 = it * BK;
        const uint32_t sa = sb + OFF_A + s * ASZ;
        const uint32_t sbu = sb + OFF_B + s * BSZ;
        #pragma unroll
        for (int j = 0; j < 8; j++) {                 // A: 1024 chunks / 128 thr
            int c = tid + j * NTHREADS;
            int r = c >> 3, c16 = c & 7;
            uint32_t dst = sa + (uint32_t)(r * 128 + ((c16 ^ (r & 7)) << 4));
            CP_ASYNC16(dst, gAb + ((size_t)r * INFEAT + k0 + c16 * 8) * 2);
        }
        #pragma unroll
        for (int j = 0; j < 8; j++) {                 // B: 1024 chunks / 128 thr
            int c = tid + j * NTHREADS;
            int r = c >> 3, c16 = c & 7;
            uint32_t dst = sbu + (uint32_t)(r * 128 + ((c16 ^ (r & 7)) << 4));
            CP_ASYNC16(dst, gBb + ((size_t)r * INFEAT + k0 + c16 * 8) * 2);
        }
    };

    // prologue: stages 0..NSTAGE-2
    #pragma unroll
    for (int p = 0; p < NSTAGE - 1; p++) { load_stage(p, p); CP_COMMIT(); }

    int sCur = 0;                       // slot of iteration `it`
    int sLoad = NSTAGE - 1;             // slot of iteration it+NSTAGE-1
    for (int it = 0; it < KITERS; ++it) {
        CP_WAIT(NSTAGE - 2);          // stage `it` resident
        __syncthreads();              // also proves iter it-1 reads complete

        if (it + NSTAGE - 1 < KITERS) load_stage(it + NSTAGE - 1, sLoad);
        CP_COMMIT();                  // commit every iter (group accounting)

        const uint32_t sa = sb + OFF_A + sCur * ASZ;
        const uint32_t sbu = sb + OFF_B + sCur * BSZ;

        #pragma unroll
        for (int ks = 0; ks < 4; ks++) {
            const uint32_t c16 = (uint32_t)(ks * 2) + chSel;
            uint32_t afr[4][4], bfr[4][4];
            #pragma unroll
            for (int tm = 0; tm < 4; tm++)
                ldsm4(afr[tm], sa + aBase[tm] + ((c16 ^ aXor[tm]) << 4));
            #pragma unroll
            for (int tp = 0; tp < 4; tp++)
                ldsm4(bfr[tp], sbu + bBase[tp] + ((c16 ^ bXor[tp]) << 4));
            #pragma unroll
            for (int tm = 0; tm < 4; tm++)
                #pragma unroll
                for (int tn = 0; tn < 8; tn++) {
                    const int tp = tn >> 1, h = tn & 1;
                    mma16816(acc[tm][tn], afr[tm], bfr[tp][h], bfr[tp][h + 2]);
                }
        }
        if (++sCur == NSTAGE) sCur = 0;
        if (++sLoad == NSTAGE) sLoad = 0;
    }

    // ---- epilogue ----
    const float scl = *scale;
    const int rr = lid >> 2;
    const int cc = (lid & 3) * 2;
    #pragma unroll
    for (int tm = 0; tm < 4; tm++) {
        const int row = m0 + mw * 64 + tm * 16 + rr;
        #pragma unroll
        for (int tn = 0; tn < 8; tn++) {
            const int col = n0 + nw * 64 + tn * 8 + cc;
            const float2 bi = *reinterpret_cast<const float2*>(bias + col);
            float2 v0, v1;
            v0.x = fmaf(acc[tm][tn][0], scl, bi.x);
            v0.y = fmaf(acc[tm][tn][1], scl, bi.y);
            v1.x = fmaf(acc[tm][tn][2], scl, bi.x);
            v1.y = fmaf(acc[tm][tn][3], scl, bi.y);
            *reinterpret_cast<float2*>(out + (size_t)row * OUTFEAT + col) = v0;
            *reinterpret_cast<float2*>(out + (size_t)(row + 8) * OUTFEAT + col) = v1;
        }
    }
}

// ---------------- launch ----------------
extern "C" void kernel_launch(void* const* d_in, const int* in_sizes, int n_in,
                              void* d_out, int out_size) {
    // Identify inputs by element count (dtype-invariant):
    const float* x = nullptr;
    const void*  wq = nullptr;
    const float* scale = nullptr;
    const float* bias = nullptr;
    for (int i = 0; i < n_in; i++) {
        const int sz = in_sizes[i];
        if (sz == TOKENS * INFEAT)       x     = (const float*)d_in[i];
        else if (sz == OUTFEAT * INFEAT) wq    = d_in[i];
        else if (sz == 1)                scale = (const float*)d_in[i];
        else if (sz == OUTFEAT)          bias  = (const float*)d_in[i];
    }
    float* out = (float*)d_out;

    __half* xh = nullptr;
    __half* wh = nullptr;
    cudaGetSymbolAddress((void**)&xh, g_xh);
    cudaGetSymbolAddress((void**)&wh, g_wh);

    // Evidence from R5/R9: ncu captures LOCAL launch index 3 -> put gemm there.
    probe_w_kernel<<<64, 256>>>((const uint32_t*)wq);                 // 0
    prep_x_kernel<<<(TOKENS * INFEAT) / 8 / 256, 256>>>(x, xh);       // 1
    prep_w_kernel<<<(OUTFEAT * INFEAT) / 8 / 256, 256>>>(wq, wh);     // 2

    cudaFuncSetAttribute(gemm_kernel, cudaFuncAttributeMaxDynamicSharedMemorySize,
                         SMEM_TOTAL);
    dim3 grid(OUTFEAT / BN, TOKENS / BM);   // (32, 64): N fastest -> A-panel L2 reuse
    gemm_kernel<<<grid, NTHREADS, SMEM_TOTAL>>>(xh, wh, scale, bias, out);  // 3
}